// round 7
// baseline (speedup 1.0000x reference)
#include <cuda_runtime.h>
#include <math.h>
#include <float.h>

// Problem constants
#define Bc    8
#define Fc    16
#define NSc   196
#define Jc    24
#define Hc    8
#define DHc   64
#define DIMc  512
#define ROTc  32
#define Nc    3160          // J + F*NS
#define MROWS (Bc*Nc)       // 25280
#define BHc   64            // B*H
#define NSP   3136          // F*NS
#define SKR   220           // J + NS (spatial key rows)

// -------- scratch (device globals; no runtime allocation) --------
__device__ float g_qkv[(size_t)MROWS * 1536];
__device__ float g_Q   [(size_t)BHc * Nc  * 64];
__device__ float g_Kraw[(size_t)BHc * Nc  * 64];
__device__ float g_Krope[(size_t)BHc * NSP * 64];
__device__ float g_V   [(size_t)BHc * Nc  * 64];
__device__ float g_AO  [(size_t)MROWS * 512];

// -------- tf32 helpers --------
__device__ __forceinline__ unsigned f2tf32(float x) {
    unsigned u;
    asm("cvt.rna.tf32.f32 %0, %1;" : "=r"(u) : "f"(x));
    return u;
}

__device__ __forceinline__ void mma_tf32(float* d, const unsigned* a, const unsigned* b) {
    asm volatile(
        "mma.sync.aligned.m16n8k8.row.col.f32.tf32.tf32.f32 "
        "{%0,%1,%2,%3}, {%4,%5,%6,%7}, {%8,%9}, {%0,%1,%2,%3};\n"
        : "+f"(d[0]), "+f"(d[1]), "+f"(d[2]), "+f"(d[3])
        : "r"(a[0]), "r"(a[1]), "r"(a[2]), "r"(a[3]),
          "r"(b[0]), "r"(b[1]));
}

// -------- TF32 tensor-core GEMM: C[M,N] = A[M,K] @ B[K,N] (+bias) --------
__global__ __launch_bounds__(256) void tgemm64x128(
        const float* __restrict__ A, const float* __restrict__ Bm,
        const float* __restrict__ bias, float* __restrict__ C,
        int M, int N, int K) {
    __shared__ unsigned As[64][20];
    __shared__ unsigned Bs[16][136];

    int tid  = threadIdx.x;
    int lane = tid & 31, warp = tid >> 5;
    int wm = warp >> 2, wn = warp & 3;
    int g  = lane >> 2, t = lane & 3;
    int row0 = blockIdx.y * 64;
    int col0 = blockIdx.x * 128;

    int am  = tid >> 2;
    int ak  = (tid & 3) * 4;
    int bk0 = tid >> 5;
    int bn  = (tid & 31) * 4;

    const float* Ap = A + (size_t)(row0 + am) * K + ak;
    const float* Bp0 = Bm + (size_t)bk0 * N + col0 + bn;
    const float* Bp1 = Bm + (size_t)(bk0 + 8) * N + col0 + bn;

    float acc[2][4][4];
    #pragma unroll
    for (int i = 0; i < 2; i++)
        #pragma unroll
        for (int j = 0; j < 4; j++)
            #pragma unroll
            for (int r = 0; r < 4; r++) acc[i][j][r] = 0.f;

    float4 ra  = *reinterpret_cast<const float4*>(Ap);
    float4 rb0 = *reinterpret_cast<const float4*>(Bp0);
    float4 rb1 = *reinterpret_cast<const float4*>(Bp1);

    for (int k0 = 0; k0 < K; k0 += 16) {
        *reinterpret_cast<uint4*>(&As[am][ak]) =
            make_uint4(f2tf32(ra.x), f2tf32(ra.y), f2tf32(ra.z), f2tf32(ra.w));
        *reinterpret_cast<uint4*>(&Bs[bk0][bn]) =
            make_uint4(f2tf32(rb0.x), f2tf32(rb0.y), f2tf32(rb0.z), f2tf32(rb0.w));
        *reinterpret_cast<uint4*>(&Bs[bk0 + 8][bn]) =
            make_uint4(f2tf32(rb1.x), f2tf32(rb1.y), f2tf32(rb1.z), f2tf32(rb1.w));
        __syncthreads();

        if (k0 + 16 < K) {
            Ap  += 16;
            Bp0 += (size_t)16 * N;
            Bp1 += (size_t)16 * N;
            ra  = *reinterpret_cast<const float4*>(Ap);
            rb0 = *reinterpret_cast<const float4*>(Bp0);
            rb1 = *reinterpret_cast<const float4*>(Bp1);
        }

        #pragma unroll
        for (int kk = 0; kk < 16; kk += 8) {
            unsigned af[2][4], bf[4][2];
            #pragma unroll
            for (int i = 0; i < 2; i++) {
                int r = wm * 32 + i * 16;
                af[i][0] = As[r + g][kk + t];
                af[i][1] = As[r + 8 + g][kk + t];
                af[i][2] = As[r + g][kk + 4 + t];
                af[i][3] = As[r + 8 + g][kk + 4 + t];
            }
            #pragma unroll
            for (int j = 0; j < 4; j++) {
                int c = wn * 32 + j * 8 + g;
                bf[j][0] = Bs[kk + t][c];
                bf[j][1] = Bs[kk + 4 + t][c];
            }
            #pragma unroll
            for (int i = 0; i < 2; i++)
                #pragma unroll
                for (int j = 0; j < 4; j++)
                    mma_tf32(acc[i][j], af[i], bf[j]);
        }
        __syncthreads();
    }

    #pragma unroll
    for (int i = 0; i < 2; i++) {
        #pragma unroll
        for (int j = 0; j < 4; j++) {
            int r = row0 + wm * 32 + i * 16 + g;
            int c = col0 + wn * 32 + j * 8 + 2 * t;
            float bb0 = 0.f, bb1 = 0.f;
            if (bias) { bb0 = bias[c]; bb1 = bias[c + 1]; }
            float2 o0 = make_float2(acc[i][j][0] + bb0, acc[i][j][1] + bb1);
            float2 o1 = make_float2(acc[i][j][2] + bb0, acc[i][j][3] + bb1);
            *reinterpret_cast<float2*>(C + (size_t)r * N + c) = o0;
            *reinterpret_cast<float2*>(C + (size_t)(r + 8) * N + c) = o1;
        }
    }
}

// -------- split qkv into head-major Q/Kraw/Krope/V, apply scale + RoPE --------
__global__ void split_rope_kernel(const float* __restrict__ sinp, const float* __restrict__ cosp) {
    int idx = blockIdx.x * blockDim.x + threadIdx.x;
    const int total = BHc * Nc * 64;
    if (idx >= total) return;
    int d  = idx & 63;
    int n  = (idx >> 6) % Nc;
    int bh = idx / (Nc * 64);
    int b = bh >> 3, h = bh & 7;

    size_t base = ((size_t)b * Nc + n) * 1536 + h * 64;
    float qv = g_qkv[base + d] * 0.125f;
    float kv = g_qkv[base + 512 + d];
    float vv = g_qkv[base + 1024 + d];

    size_t o = ((size_t)bh * Nc + n) * 64 + d;
    g_Kraw[o] = kv;
    g_V[o]    = vv;

    float qo = qv, ko = kv;
    if (n >= Jc) {
        int m = n - Jc;
        int s = m % NSc;
        if (d < ROTc) {
            float c  = cosp[s * ROTc + d];
            float si = sinp[s * ROTc + d];
            if ((d & 1) == 0) {
                float qp = g_qkv[base + d + 1] * 0.125f;
                float kp = g_qkv[base + 512 + d + 1];
                qo = qv * c - qp * si;
                ko = kv * c - kp * si;
            } else {
                float qp = g_qkv[base + d - 1] * 0.125f;
                float kp = g_qkv[base + 512 + d - 1];
                qo = qv * c + qp * si;
                ko = kv * c + kp * si;
            }
        }
        g_Krope[((size_t)bh * NSP + m) * 64 + d] = ko;
    }
    g_Q[o] = qo;
}

// ============ joints attention (flash, tf32 MMA): block per bh ============
// S^T[128,32] = Kchunk[128,64] @ Qt[64,32]; online softmax; O += P@V.
__global__ __launch_bounds__(256) void joints_attn_mma() {
    extern __shared__ float smem[];
    unsigned* uK = (unsigned*)smem;           // 128*68
    unsigned* uV = uK + 128 * 68;             // 128*68
    unsigned* uQ = uV + 128 * 68;             // 64*36
    float*    St = (float*)(uQ + 64 * 36);    // 128*36
    unsigned* uP = (unsigned*)(St + 128 * 36);// 32*133
    float*   red = (float*)(uP + 32 * 133);   // 256
    float*  mrow = red + 256;                 // 32
    float*   scl = mrow + 32;                 // 32
    float*  lrow = scl + 32;                  // 32

    int bh = blockIdx.x;
    int b = bh >> 3, h = bh & 7;
    int tid = threadIdx.x, lane = tid & 31, warp = tid >> 5;
    int g = lane >> 2, t = lane & 3;

    const float* Kb = g_Kraw + (size_t)bh * Nc * 64;
    const float* Vb = g_V    + (size_t)bh * Nc * 64;

    if (tid < 32) { mrow[tid] = -FLT_MAX; lrow[tid] = 0.f; }

    for (int i = tid; i < 32 * 64; i += 256) {
        int q = i >> 6, d = i & 63;
        int qq = (q < Jc) ? q : (Jc - 1);
        uQ[d * 36 + q] = f2tf32(g_Q[((size_t)bh * Nc + qq) * 64 + d]);
    }

    float oc[2][4] = {{0,0,0,0},{0,0,0,0}};

    for (int c0 = 0; c0 < Nc; c0 += 128) {
        int kn = min(128, Nc - c0);
        __syncthreads();
        for (int i = tid; i < kn * 64; i += 256) {
            int r = i >> 6, d = i & 63;
            uK[r * 68 + d] = f2tf32(Kb[(size_t)(c0 + r) * 64 + d]);
            uV[r * 68 + d] = f2tf32(Vb[(size_t)(c0 + r) * 64 + d]);
        }
        __syncthreads();

        // S^T MMA: 8 m-tiles x 4 n-tiles
        for (int tIdx = warp; tIdx < 32; tIdx += 8) {
            int mi = tIdx & 7, ni = tIdx >> 3;
            float c[4] = {0,0,0,0};
            #pragma unroll
            for (int kk = 0; kk < 8; kk++) {
                unsigned a[4], bfr[2];
                const unsigned* Ab = uK + (mi * 16) * 68 + kk * 8;
                a[0] = Ab[g * 68 + t];       a[1] = Ab[(g + 8) * 68 + t];
                a[2] = Ab[g * 68 + 4 + t];   a[3] = Ab[(g + 8) * 68 + 4 + t];
                const unsigned* Bb = uQ + (kk * 8) * 36 + ni * 8;
                bfr[0] = Bb[t * 36 + g];     bfr[1] = Bb[(4 + t) * 36 + g];
                mma_tf32(c, a, bfr);
            }
            float* Sb = St + (mi * 16) * 36 + ni * 8;
            *(float2*)(Sb + g * 36 + 2 * t)       = make_float2(c[0], c[1]);
            *(float2*)(Sb + (g + 8) * 36 + 2 * t) = make_float2(c[2], c[3]);
        }
        __syncthreads();

        // online softmax update
        {
            int q = tid & 31, s = tid >> 5;
            int j0 = s * 16, j1 = min(j0 + 16, kn);
            float lm = -FLT_MAX;
            for (int j = j0; j < j1; j++) lm = fmaxf(lm, St[j * 36 + q]);
            red[s * 32 + q] = lm;
            __syncthreads();
            float cm = red[q];
            #pragma unroll
            for (int ss = 1; ss < 8; ss++) cm = fmaxf(cm, red[ss * 32 + q]);
            float mold = mrow[q];
            float mnew = fmaxf(mold, cm);
            __syncthreads();
            float ls = 0.f;
            for (int j = j0; j < j1; j++) {
                float e = __expf(St[j * 36 + q] - mnew);
                ls += e;
                uP[q * 133 + j] = f2tf32(e);
            }
            for (int j = j1; j < j0 + 16; j++) uP[q * 133 + j] = 0u;
            red[s * 32 + q] = ls;
            __syncthreads();
            if (s == 0) {
                float tot = 0.f;
                #pragma unroll
                for (int ss = 0; ss < 8; ss++) tot += red[ss * 32 + q];
                float sc = __expf(mold - mnew);
                lrow[q] = lrow[q] * sc + tot;
                mrow[q] = mnew;
                scl[q]  = sc;
            }
        }
        __syncthreads();

        // rescale + accumulate O += P @ V  (2 tiles per warp: 2m x 8n grid)
        #pragma unroll
        for (int ti = 0; ti < 2; ti++) {
            int tIdx = warp + ti * 8;
            int mi = tIdx & 1, ni = tIdx >> 1;
            int q = mi * 16 + g;
            float s0 = scl[q], s1 = scl[q + 8];
            oc[ti][0] *= s0; oc[ti][1] *= s0; oc[ti][2] *= s1; oc[ti][3] *= s1;
            for (int kk = 0; kk < 16; kk++) {
                unsigned a[4], bfr[2];
                const unsigned* Ab = uP + (mi * 16) * 133 + kk * 8;
                a[0] = Ab[g * 133 + t];      a[1] = Ab[(g + 8) * 133 + t];
                a[2] = Ab[g * 133 + 4 + t];  a[3] = Ab[(g + 8) * 133 + 4 + t];
                const unsigned* Bb = uV + (kk * 8) * 68 + ni * 8;
                bfr[0] = Bb[t * 68 + g];     bfr[1] = Bb[(4 + t) * 68 + g];
                mma_tf32(oc[ti], a, bfr);
            }
        }
    }
    __syncthreads();

    #pragma unroll
    for (int ti = 0; ti < 2; ti++) {
        int tIdx = warp + ti * 8;
        int mi = tIdx & 1, ni = tIdx >> 1;
        int q = mi * 16 + g, d = ni * 8 + 2 * t;
        if (q < Jc) {
            float inv = 1.f / lrow[q];
            *(float2*)(g_AO + ((size_t)b * Nc + q) * 512 + h * 64 + d) =
                make_float2(oc[ti][0] * inv, oc[ti][1] * inv);
        }
        if (q + 8 < Jc) {
            float inv = 1.f / lrow[q + 8];
            *(float2*)(g_AO + ((size_t)b * Nc + q + 8) * 512 + h * 64 + d) =
                make_float2(oc[ti][2] * inv, oc[ti][3] * inv);
        }
    }
}

// ============ spatial attention (tf32 MMA): block per (bh,f) ============
// K/V resident in smem (224 rows incl 4 zero-pad); loop 7 q-tiles of 32.
__global__ __launch_bounds__(256) void spatial_attn_mma() {
    extern __shared__ float smem[];
    unsigned* uK = (unsigned*)smem;             // 224*68
    unsigned* uV = uK + 224 * 68;               // 224*68
    unsigned* uQ = uV + 224 * 68;               // 64*36
    float*    St = (float*)(uQ + 64 * 36);      // 224*36
    unsigned* uP = (unsigned*)(St + 224 * 36);  // 32*233
    float*   red = (float*)(uP + 32 * 233);     // 256
    float*  srow = red + 256;                   // 32

    int blk = blockIdx.x;
    int bh = blk >> 4, f = blk & 15;
    int b = bh >> 3, h = bh & 7;
    int tid = threadIdx.x, lane = tid & 31, warp = tid >> 5;
    int g = lane >> 2, t = lane & 3;

    const float* Krb = g_Kraw  + (size_t)bh * Nc  * 64;
    const float* Kpb = g_Krope + (size_t)bh * NSP * 64;
    const float* Vb  = g_V     + (size_t)bh * Nc  * 64;

    for (int i = tid; i < 224 * 64; i += 256) {
        int r = i >> 6, d = i & 63;
        float kv = 0.f, vv = 0.f;
        if (r < Jc) { kv = Krb[r * 64 + d]; vv = Vb[r * 64 + d]; }
        else if (r < SKR) {
            int m = f * NSc + (r - Jc);
            kv = Kpb[(size_t)m * 64 + d];
            vv = Vb[(size_t)(Jc + m) * 64 + d];
        }
        uK[r * 68 + d] = f2tf32(kv);
        uV[r * 68 + d] = f2tf32(vv);
    }
    size_t qrow0 = (size_t)bh * Nc + Jc + f * NSc;
    __syncthreads();

    for (int q0 = 0; q0 < NSc; q0 += 32) {
        for (int i = tid; i < 32 * 64; i += 256) {
            int q = i >> 6, d = i & 63;
            int qq = q0 + q; if (qq > NSc - 1) qq = NSc - 1;
            uQ[d * 36 + q] = f2tf32(g_Q[(qrow0 + qq) * 64 + d]);
        }
        __syncthreads();

        // S^T = K @ Qt : 14 m-tiles x 4 n-tiles = 56 tiles
        for (int tIdx = warp; tIdx < 56; tIdx += 8) {
            int mi = tIdx % 14, ni = tIdx / 14;
            float c[4] = {0,0,0,0};
            #pragma unroll
            for (int kk = 0; kk < 8; kk++) {
                unsigned a[4], bfr[2];
                const unsigned* Ab = uK + (mi * 16) * 68 + kk * 8;
                a[0] = Ab[g * 68 + t];       a[1] = Ab[(g + 8) * 68 + t];
                a[2] = Ab[g * 68 + 4 + t];   a[3] = Ab[(g + 8) * 68 + 4 + t];
                const unsigned* Bb = uQ + (kk * 8) * 36 + ni * 8;
                bfr[0] = Bb[t * 36 + g];     bfr[1] = Bb[(4 + t) * 36 + g];
                mma_tf32(c, a, bfr);
            }
            float* Sb = St + (mi * 16) * 36 + ni * 8;
            *(float2*)(Sb + g * 36 + 2 * t)       = make_float2(c[0], c[1]);
            *(float2*)(Sb + (g + 8) * 36 + 2 * t) = make_float2(c[2], c[3]);
        }
        __syncthreads();

        // softmax (per q over 220 keys), write unnormalized exp to uP, 1/sum in srow
        {
            int q = tid & 31, s = tid >> 5;
            int j0 = s * 28, j1 = min(j0 + 28, SKR);
            float lm = -FLT_MAX;
            for (int j = j0; j < j1; j++) lm = fmaxf(lm, St[j * 36 + q]);
            red[s * 32 + q] = lm;
            __syncthreads();
            float m = red[q];
            #pragma unroll
            for (int ss = 1; ss < 8; ss++) m = fmaxf(m, red[ss * 32 + q]);
            __syncthreads();
            float ls = 0.f;
            for (int j = j0; j < j1; j++) {
                float e = __expf(St[j * 36 + q] - m);
                ls += e;
                uP[q * 233 + j] = f2tf32(e);
            }
            if (s == 7) for (int j = SKR; j < 224; j++) uP[q * 233 + j] = 0u;
            red[s * 32 + q] = ls;
            __syncthreads();
            if (s == 0) {
                float tot = 0.f;
                #pragma unroll
                for (int ss = 0; ss < 8; ss++) tot += red[ss * 32 + q];
                srow[q] = 1.f / tot;
            }
        }
        __syncthreads();

        // O = P @ V : 2 m-tiles x 8 n-tiles
        for (int tIdx = warp; tIdx < 16; tIdx += 8) {
            int mi = tIdx & 1, ni = tIdx >> 1;
            float c[4] = {0,0,0,0};
            for (int kk = 0; kk < 28; kk++) {
                unsigned a[4], bfr[2];
                const unsigned* Ab = uP + (mi * 16) * 233 + kk * 8;
                a[0] = Ab[g * 233 + t];      a[1] = Ab[(g + 8) * 233 + t];
                a[2] = Ab[g * 233 + 4 + t];  a[3] = Ab[(g + 8) * 233 + 4 + t];
                const unsigned* Bb = uV + (kk * 8) * 68 + ni * 8;
                bfr[0] = Bb[t * 68 + g];     bfr[1] = Bb[(4 + t) * 68 + g];
                mma_tf32(c, a, bfr);
            }
            int q = mi * 16 + g, d = ni * 8 + 2 * t;
            int qq = q0 + q;
            if (qq < NSc) {
                float inv = srow[q];
                int n = Jc + f * NSc + qq;
                *(float2*)(g_AO + ((size_t)b * Nc + n) * 512 + h * 64 + d) =
                    make_float2(c[0] * inv, c[1] * inv);
            }
            if (qq + 8 < NSc) {
                float inv = srow[q + 8];
                int n = Jc + f * NSc + qq + 8;
                *(float2*)(g_AO + ((size_t)b * Nc + n) * 512 + h * 64 + d) =
                    make_float2(c[2] * inv, c[3] * inv);
            }
        }
        __syncthreads();
    }
}

// -------- launch --------
extern "C" void kernel_launch(void* const* d_in, const int* in_sizes, int n_in,
                              void* d_out, int out_size) {
    const float* x     = (const float*)d_in[0];
    const float* w_qkv = (const float*)d_in[1];
    const float* w_out = (const float*)d_in[2];
    const float* b_out = (const float*)d_in[3];
    const float* sinp  = (const float*)d_in[4];
    const float* cosp  = (const float*)d_in[5];
    float* out = (float*)d_out;

    void *pqkv = nullptr, *pAO = nullptr;
    cudaGetSymbolAddress(&pqkv, g_qkv);
    cudaGetSymbolAddress(&pAO,  g_AO);

    const int JSMEM = (128*68*2 + 64*36 + 128*36 + 32*133 + 256 + 96) * 4;
    const int SSMEM = (224*68*2 + 64*36 + 224*36 + 32*233 + 256 + 32) * 4;
    cudaFuncSetAttribute(joints_attn_mma,
                         cudaFuncAttributeMaxDynamicSharedMemorySize, JSMEM);
    cudaFuncSetAttribute(spatial_attn_mma,
                         cudaFuncAttributeMaxDynamicSharedMemorySize, SSMEM);

    // 1) QKV GEMM
    dim3 g1(1536 / 128, MROWS / 64);
    tgemm64x128<<<g1, 256>>>(x, w_qkv, nullptr, (float*)pqkv, MROWS, 1536, 512);

    // 2) split + scale + RoPE
    int total = BHc * Nc * 64;
    split_rope_kernel<<<(total + 255) / 256, 256>>>(sinp, cosp);

    // 3) joints attention (flash MMA)
    joints_attn_mma<<<BHc, 256, JSMEM>>>();

    // 4) spatial attention (MMA)
    spatial_attn_mma<<<BHc * Fc, 256, SSMEM>>>();

    // 5) output GEMM
    dim3 g2(512 / 128, MROWS / 64);
    tgemm64x128<<<g2, 256>>>((const float*)pAO, w_out, b_out, out, MROWS, 512, 512);
}

// round 8
// speedup vs baseline: 1.0081x; 1.0081x over previous
#include <cuda_runtime.h>
#include <math.h>
#include <float.h>

// Problem constants
#define Bc    8
#define Fc    16
#define NSc   196
#define Jc    24
#define Hc    8
#define DHc   64
#define DIMc  512
#define ROTc  32
#define Nc    3160          // J + F*NS
#define MROWS (Bc*Nc)       // 25280
#define BHc   64            // B*H
#define NSP   3136          // F*NS
#define SKR   220           // J + NS (spatial key rows)

// -------- scratch (device globals; no runtime allocation) --------
__device__ float g_qkv[(size_t)MROWS * 1536];
__device__ float g_Q   [(size_t)BHc * Nc  * 64];
__device__ float g_Kraw[(size_t)BHc * Nc  * 64];
__device__ float g_Krope[(size_t)BHc * NSP * 64];
__device__ float g_V   [(size_t)BHc * Nc  * 64];
__device__ float g_AO  [(size_t)MROWS * 512];

// -------- tf32 helpers --------
__device__ __forceinline__ unsigned f2tf32(float x) {
    unsigned u;
    asm("cvt.rna.tf32.f32 %0, %1;" : "=r"(u) : "f"(x));
    return u;
}

__device__ __forceinline__ void mma_tf32(float* d, const unsigned* a, const unsigned* b) {
    asm volatile(
        "mma.sync.aligned.m16n8k8.row.col.f32.tf32.tf32.f32 "
        "{%0,%1,%2,%3}, {%4,%5,%6,%7}, {%8,%9}, {%0,%1,%2,%3};\n"
        : "+f"(d[0]), "+f"(d[1]), "+f"(d[2]), "+f"(d[3])
        : "r"(a[0]), "r"(a[1]), "r"(a[2]), "r"(a[3]),
          "r"(b[0]), "r"(b[1]));
}

// -------- TF32 tensor-core GEMM: C[M,N] = A[M,K] @ B[K,N] (+bias) --------
__global__ __launch_bounds__(256) void tgemm64x128(
        const float* __restrict__ A, const float* __restrict__ Bm,
        const float* __restrict__ bias, float* __restrict__ C,
        int M, int N, int K) {
    __shared__ unsigned As[64][20];
    __shared__ unsigned Bs[16][136];

    int tid  = threadIdx.x;
    int lane = tid & 31, warp = tid >> 5;
    int wm = warp >> 2, wn = warp & 3;
    int g  = lane >> 2, t = lane & 3;
    int row0 = blockIdx.y * 64;
    int col0 = blockIdx.x * 128;

    int am  = tid >> 2;
    int ak  = (tid & 3) * 4;
    int bk0 = tid >> 5;
    int bn  = (tid & 31) * 4;

    const float* Ap = A + (size_t)(row0 + am) * K + ak;
    const float* Bp0 = Bm + (size_t)bk0 * N + col0 + bn;
    const float* Bp1 = Bm + (size_t)(bk0 + 8) * N + col0 + bn;

    float acc[2][4][4];
    #pragma unroll
    for (int i = 0; i < 2; i++)
        #pragma unroll
        for (int j = 0; j < 4; j++)
            #pragma unroll
            for (int r = 0; r < 4; r++) acc[i][j][r] = 0.f;

    float4 ra  = *reinterpret_cast<const float4*>(Ap);
    float4 rb0 = *reinterpret_cast<const float4*>(Bp0);
    float4 rb1 = *reinterpret_cast<const float4*>(Bp1);

    for (int k0 = 0; k0 < K; k0 += 16) {
        *reinterpret_cast<uint4*>(&As[am][ak]) =
            make_uint4(f2tf32(ra.x), f2tf32(ra.y), f2tf32(ra.z), f2tf32(ra.w));
        *reinterpret_cast<uint4*>(&Bs[bk0][bn]) =
            make_uint4(f2tf32(rb0.x), f2tf32(rb0.y), f2tf32(rb0.z), f2tf32(rb0.w));
        *reinterpret_cast<uint4*>(&Bs[bk0 + 8][bn]) =
            make_uint4(f2tf32(rb1.x), f2tf32(rb1.y), f2tf32(rb1.z), f2tf32(rb1.w));
        __syncthreads();

        if (k0 + 16 < K) {
            Ap  += 16;
            Bp0 += (size_t)16 * N;
            Bp1 += (size_t)16 * N;
            ra  = *reinterpret_cast<const float4*>(Ap);
            rb0 = *reinterpret_cast<const float4*>(Bp0);
            rb1 = *reinterpret_cast<const float4*>(Bp1);
        }

        #pragma unroll
        for (int kk = 0; kk < 16; kk += 8) {
            unsigned af[2][4], bf[4][2];
            #pragma unroll
            for (int i = 0; i < 2; i++) {
                int r = wm * 32 + i * 16;
                af[i][0] = As[r + g][kk + t];
                af[i][1] = As[r + 8 + g][kk + t];
                af[i][2] = As[r + g][kk + 4 + t];
                af[i][3] = As[r + 8 + g][kk + 4 + t];
            }
            #pragma unroll
            for (int j = 0; j < 4; j++) {
                int c = wn * 32 + j * 8 + g;
                bf[j][0] = Bs[kk + t][c];
                bf[j][1] = Bs[kk + 4 + t][c];
            }
            #pragma unroll
            for (int i = 0; i < 2; i++)
                #pragma unroll
                for (int j = 0; j < 4; j++)
                    mma_tf32(acc[i][j], af[i], bf[j]);
        }
        __syncthreads();
    }

    #pragma unroll
    for (int i = 0; i < 2; i++) {
        #pragma unroll
        for (int j = 0; j < 4; j++) {
            int r = row0 + wm * 32 + i * 16 + g;
            int c = col0 + wn * 32 + j * 8 + 2 * t;
            float bb0 = 0.f, bb1 = 0.f;
            if (bias) { bb0 = bias[c]; bb1 = bias[c + 1]; }
            float2 o0 = make_float2(acc[i][j][0] + bb0, acc[i][j][1] + bb1);
            float2 o1 = make_float2(acc[i][j][2] + bb0, acc[i][j][3] + bb1);
            *reinterpret_cast<float2*>(C + (size_t)r * N + c) = o0;
            *reinterpret_cast<float2*>(C + (size_t)(r + 8) * N + c) = o1;
        }
    }
}

// -------- split qkv into head-major Q/Kraw/Krope/V, apply scale + RoPE --------
__global__ void split_rope_kernel(const float* __restrict__ sinp, const float* __restrict__ cosp) {
    int idx = blockIdx.x * blockDim.x + threadIdx.x;
    const int total = BHc * Nc * 64;
    if (idx >= total) return;
    int d  = idx & 63;
    int n  = (idx >> 6) % Nc;
    int bh = idx / (Nc * 64);
    int b = bh >> 3, h = bh & 7;

    size_t base = ((size_t)b * Nc + n) * 1536 + h * 64;
    float qv = g_qkv[base + d] * 0.125f;
    float kv = g_qkv[base + 512 + d];
    float vv = g_qkv[base + 1024 + d];

    size_t o = ((size_t)bh * Nc + n) * 64 + d;
    g_Kraw[o] = kv;
    g_V[o]    = vv;

    float qo = qv, ko = kv;
    if (n >= Jc) {
        int m = n - Jc;
        int s = m % NSc;
        if (d < ROTc) {
            float c  = cosp[s * ROTc + d];
            float si = sinp[s * ROTc + d];
            if ((d & 1) == 0) {
                float qp = g_qkv[base + d + 1] * 0.125f;
                float kp = g_qkv[base + 512 + d + 1];
                qo = qv * c - qp * si;
                ko = kv * c - kp * si;
            } else {
                float qp = g_qkv[base + d - 1] * 0.125f;
                float kp = g_qkv[base + 512 + d - 1];
                qo = qv * c + qp * si;
                ko = kv * c + kp * si;
            }
        }
        g_Krope[((size_t)bh * NSP + m) * 64 + d] = ko;
    }
    g_Q[o] = qo;
}

// ============ joints attention (flash, tf32 MMA): block per bh ============
// S^T[128,32] = Kchunk[128,64] @ Qt[64,32]; online softmax; O += P@V.
__global__ __launch_bounds__(256) void joints_attn_mma() {
    extern __shared__ float smem[];
    unsigned* uK = (unsigned*)smem;           // 128*68
    unsigned* uV = uK + 128 * 68;             // 128*68
    unsigned* uQ = uV + 128 * 68;             // 64*36
    float*    St = (float*)(uQ + 64 * 36);    // 128*36
    unsigned* uP = (unsigned*)(St + 128 * 36);// 32*133
    float*   red = (float*)(uP + 32 * 133);   // 256
    float*  mrow = red + 256;                 // 32
    float*   scl = mrow + 32;                 // 32
    float*  lrow = scl + 32;                  // 32

    int bh = blockIdx.x;
    int b = bh >> 3, h = bh & 7;
    int tid = threadIdx.x, lane = tid & 31, warp = tid >> 5;
    int g = lane >> 2, t = lane & 3;

    const float* Kb = g_Kraw + (size_t)bh * Nc * 64;
    const float* Vb = g_V    + (size_t)bh * Nc * 64;

    if (tid < 32) { mrow[tid] = -FLT_MAX; lrow[tid] = 0.f; }

    for (int i = tid; i < 32 * 64; i += 256) {
        int q = i >> 6, d = i & 63;
        int qq = (q < Jc) ? q : (Jc - 1);
        uQ[d * 36 + q] = f2tf32(g_Q[((size_t)bh * Nc + qq) * 64 + d]);
    }

    float oc[2][4] = {{0,0,0,0},{0,0,0,0}};

    for (int c0 = 0; c0 < Nc; c0 += 128) {
        int kn = min(128, Nc - c0);
        __syncthreads();
        for (int i = tid; i < kn * 64; i += 256) {
            int r = i >> 6, d = i & 63;
            uK[r * 68 + d] = f2tf32(Kb[(size_t)(c0 + r) * 64 + d]);
            uV[r * 68 + d] = f2tf32(Vb[(size_t)(c0 + r) * 64 + d]);
        }
        __syncthreads();

        // S^T MMA: 8 m-tiles x 4 n-tiles
        for (int tIdx = warp; tIdx < 32; tIdx += 8) {
            int mi = tIdx & 7, ni = tIdx >> 3;
            float c[4] = {0,0,0,0};
            #pragma unroll
            for (int kk = 0; kk < 8; kk++) {
                unsigned a[4], bfr[2];
                const unsigned* Ab = uK + (mi * 16) * 68 + kk * 8;
                a[0] = Ab[g * 68 + t];       a[1] = Ab[(g + 8) * 68 + t];
                a[2] = Ab[g * 68 + 4 + t];   a[3] = Ab[(g + 8) * 68 + 4 + t];
                const unsigned* Bb = uQ + (kk * 8) * 36 + ni * 8;
                bfr[0] = Bb[t * 36 + g];     bfr[1] = Bb[(4 + t) * 36 + g];
                mma_tf32(c, a, bfr);
            }
            float* Sb = St + (mi * 16) * 36 + ni * 8;
            *(float2*)(Sb + g * 36 + 2 * t)       = make_float2(c[0], c[1]);
            *(float2*)(Sb + (g + 8) * 36 + 2 * t) = make_float2(c[2], c[3]);
        }
        __syncthreads();

        // online softmax update
        {
            int q = tid & 31, s = tid >> 5;
            int j0 = s * 16, j1 = min(j0 + 16, kn);
            float lm = -FLT_MAX;
            for (int j = j0; j < j1; j++) lm = fmaxf(lm, St[j * 36 + q]);
            red[s * 32 + q] = lm;
            __syncthreads();
            float cm = red[q];
            #pragma unroll
            for (int ss = 1; ss < 8; ss++) cm = fmaxf(cm, red[ss * 32 + q]);
            float mold = mrow[q];
            float mnew = fmaxf(mold, cm);
            __syncthreads();
            float ls = 0.f;
            for (int j = j0; j < j1; j++) {
                float e = __expf(St[j * 36 + q] - mnew);
                ls += e;
                uP[q * 133 + j] = f2tf32(e);
            }
            for (int j = j1; j < j0 + 16; j++) uP[q * 133 + j] = 0u;
            red[s * 32 + q] = ls;
            __syncthreads();
            if (s == 0) {
                float tot = 0.f;
                #pragma unroll
                for (int ss = 0; ss < 8; ss++) tot += red[ss * 32 + q];
                float sc = __expf(mold - mnew);
                lrow[q] = lrow[q] * sc + tot;
                mrow[q] = mnew;
                scl[q]  = sc;
            }
        }
        __syncthreads();

        // rescale + accumulate O += P @ V  (2 tiles per warp: 2m x 8n grid)
        #pragma unroll
        for (int ti = 0; ti < 2; ti++) {
            int tIdx = warp + ti * 8;
            int mi = tIdx & 1, ni = tIdx >> 1;
            int q = mi * 16 + g;
            float s0 = scl[q], s1 = scl[q + 8];
            oc[ti][0] *= s0; oc[ti][1] *= s0; oc[ti][2] *= s1; oc[ti][3] *= s1;
            for (int kk = 0; kk < 16; kk++) {
                unsigned a[4], bfr[2];
                const unsigned* Ab = uP + (mi * 16) * 133 + kk * 8;
                a[0] = Ab[g * 133 + t];      a[1] = Ab[(g + 8) * 133 + t];
                a[2] = Ab[g * 133 + 4 + t];  a[3] = Ab[(g + 8) * 133 + 4 + t];
                const unsigned* Bb = uV + (kk * 8) * 68 + ni * 8;
                bfr[0] = Bb[t * 68 + g];     bfr[1] = Bb[(4 + t) * 68 + g];
                mma_tf32(oc[ti], a, bfr);
            }
        }
    }
    __syncthreads();

    #pragma unroll
    for (int ti = 0; ti < 2; ti++) {
        int tIdx = warp + ti * 8;
        int mi = tIdx & 1, ni = tIdx >> 1;
        int q = mi * 16 + g, d = ni * 8 + 2 * t;
        if (q < Jc) {
            float inv = 1.f / lrow[q];
            *(float2*)(g_AO + ((size_t)b * Nc + q) * 512 + h * 64 + d) =
                make_float2(oc[ti][0] * inv, oc[ti][1] * inv);
        }
        if (q + 8 < Jc) {
            float inv = 1.f / lrow[q + 8];
            *(float2*)(g_AO + ((size_t)b * Nc + q + 8) * 512 + h * 64 + d) =
                make_float2(oc[ti][2] * inv, oc[ti][3] * inv);
        }
    }
}

// ============ spatial attention (tf32 MMA): block per (bh,f) ============
// K/V resident in smem (224 rows incl 4 zero-pad); loop 7 q-tiles of 32.
__global__ __launch_bounds__(256) void spatial_attn_mma() {
    extern __shared__ float smem[];
    unsigned* uK = (unsigned*)smem;             // 224*68
    unsigned* uV = uK + 224 * 68;               // 224*68
    unsigned* uQ = uV + 224 * 68;               // 64*36
    float*    St = (float*)(uQ + 64 * 36);      // 224*36
    unsigned* uP = (unsigned*)(St + 224 * 36);  // 32*233
    float*   red = (float*)(uP + 32 * 233);     // 256
    float*  srow = red + 256;                   // 32

    int blk = blockIdx.x;
    int bh = blk >> 4, f = blk & 15;
    int b = bh >> 3, h = bh & 7;
    int tid = threadIdx.x, lane = tid & 31, warp = tid >> 5;
    int g = lane >> 2, t = lane & 3;

    const float* Krb = g_Kraw  + (size_t)bh * Nc  * 64;
    const float* Kpb = g_Krope + (size_t)bh * NSP * 64;
    const float* Vb  = g_V     + (size_t)bh * Nc  * 64;

    for (int i = tid; i < 224 * 64; i += 256) {
        int r = i >> 6, d = i & 63;
        float kv = 0.f, vv = 0.f;
        if (r < Jc) { kv = Krb[r * 64 + d]; vv = Vb[r * 64 + d]; }
        else if (r < SKR) {
            int m = f * NSc + (r - Jc);
            kv = Kpb[(size_t)m * 64 + d];
            vv = Vb[(size_t)(Jc + m) * 64 + d];
        }
        uK[r * 68 + d] = f2tf32(kv);
        uV[r * 68 + d] = f2tf32(vv);
    }
    size_t qrow0 = (size_t)bh * Nc + Jc + f * NSc;
    __syncthreads();

    for (int q0 = 0; q0 < NSc; q0 += 32) {
        for (int i = tid; i < 32 * 64; i += 256) {
            int q = i >> 6, d = i & 63;
            int qq = q0 + q; if (qq > NSc - 1) qq = NSc - 1;
            uQ[d * 36 + q] = f2tf32(g_Q[(qrow0 + qq) * 64 + d]);
        }
        __syncthreads();

        // S^T = K @ Qt : 14 m-tiles x 4 n-tiles = 56 tiles
        for (int tIdx = warp; tIdx < 56; tIdx += 8) {
            int mi = tIdx % 14, ni = tIdx / 14;
            float c[4] = {0,0,0,0};
            #pragma unroll
            for (int kk = 0; kk < 8; kk++) {
                unsigned a[4], bfr[2];
                const unsigned* Ab = uK + (mi * 16) * 68 + kk * 8;
                a[0] = Ab[g * 68 + t];       a[1] = Ab[(g + 8) * 68 + t];
                a[2] = Ab[g * 68 + 4 + t];   a[3] = Ab[(g + 8) * 68 + 4 + t];
                const unsigned* Bb = uQ + (kk * 8) * 36 + ni * 8;
                bfr[0] = Bb[t * 36 + g];     bfr[1] = Bb[(4 + t) * 36 + g];
                mma_tf32(c, a, bfr);
            }
            float* Sb = St + (mi * 16) * 36 + ni * 8;
            *(float2*)(Sb + g * 36 + 2 * t)       = make_float2(c[0], c[1]);
            *(float2*)(Sb + (g + 8) * 36 + 2 * t) = make_float2(c[2], c[3]);
        }
        __syncthreads();

        // softmax (per q over 220 keys), write unnormalized exp to uP, 1/sum in srow
        {
            int q = tid & 31, s = tid >> 5;
            int j0 = s * 28, j1 = min(j0 + 28, SKR);
            float lm = -FLT_MAX;
            for (int j = j0; j < j1; j++) lm = fmaxf(lm, St[j * 36 + q]);
            red[s * 32 + q] = lm;
            __syncthreads();
            float m = red[q];
            #pragma unroll
            for (int ss = 1; ss < 8; ss++) m = fmaxf(m, red[ss * 32 + q]);
            __syncthreads();
            float ls = 0.f;
            for (int j = j0; j < j1; j++) {
                float e = __expf(St[j * 36 + q] - m);
                ls += e;
                uP[q * 233 + j] = f2tf32(e);
            }
            if (s == 7) for (int j = SKR; j < 224; j++) uP[q * 233 + j] = 0u;
            red[s * 32 + q] = ls;
            __syncthreads();
            if (s == 0) {
                float tot = 0.f;
                #pragma unroll
                for (int ss = 0; ss < 8; ss++) tot += red[ss * 32 + q];
                srow[q] = 1.f / tot;
            }
        }
        __syncthreads();

        // O = P @ V : 2 m-tiles x 8 n-tiles
        for (int tIdx = warp; tIdx < 16; tIdx += 8) {
            int mi = tIdx & 1, ni = tIdx >> 1;
            float c[4] = {0,0,0,0};
            for (int kk = 0; kk < 28; kk++) {
                unsigned a[4], bfr[2];
                const unsigned* Ab = uP + (mi * 16) * 233 + kk * 8;
                a[0] = Ab[g * 233 + t];      a[1] = Ab[(g + 8) * 233 + t];
                a[2] = Ab[g * 233 + 4 + t];  a[3] = Ab[(g + 8) * 233 + 4 + t];
                const unsigned* Bb = uV + (kk * 8) * 68 + ni * 8;
                bfr[0] = Bb[t * 68 + g];     bfr[1] = Bb[(4 + t) * 68 + g];
                mma_tf32(c, a, bfr);
            }
            int q = mi * 16 + g, d = ni * 8 + 2 * t;
            int qq = q0 + q;
            if (qq < NSc) {
                float inv = srow[q];
                int n = Jc + f * NSc + qq;
                *(float2*)(g_AO + ((size_t)b * Nc + n) * 512 + h * 64 + d) =
                    make_float2(c[0] * inv, c[1] * inv);
            }
            if (qq + 8 < NSc) {
                float inv = srow[q + 8];
                int n = Jc + f * NSc + qq + 8;
                *(float2*)(g_AO + ((size_t)b * Nc + n) * 512 + h * 64 + d) =
                    make_float2(c[2] * inv, c[3] * inv);
            }
        }
        __syncthreads();
    }
}

// -------- launch --------
extern "C" void kernel_launch(void* const* d_in, const int* in_sizes, int n_in,
                              void* d_out, int out_size) {
    const float* x     = (const float*)d_in[0];
    const float* w_qkv = (const float*)d_in[1];
    const float* w_out = (const float*)d_in[2];
    const float* b_out = (const float*)d_in[3];
    const float* sinp  = (const float*)d_in[4];
    const float* cosp  = (const float*)d_in[5];
    float* out = (float*)d_out;

    void *pqkv = nullptr, *pAO = nullptr;
    cudaGetSymbolAddress(&pqkv, g_qkv);
    cudaGetSymbolAddress(&pAO,  g_AO);

    const int JSMEM = (128*68*2 + 64*36 + 128*36 + 32*133 + 256 + 96) * 4;
    const int SSMEM = (224*68*2 + 64*36 + 224*36 + 32*233 + 256 + 32) * 4;
    cudaFuncSetAttribute(joints_attn_mma,
                         cudaFuncAttributeMaxDynamicSharedMemorySize, JSMEM);
    cudaFuncSetAttribute(spatial_attn_mma,
                         cudaFuncAttributeMaxDynamicSharedMemorySize, SSMEM);

    // 1) QKV GEMM
    dim3 g1(1536 / 128, MROWS / 64);
    tgemm64x128<<<g1, 256>>>(x, w_qkv, nullptr, (float*)pqkv, MROWS, 1536, 512);

    // 2) split + scale + RoPE
    int total = BHc * Nc * 64;
    split_rope_kernel<<<(total + 255) / 256, 256>>>(sinp, cosp);

    // 3) joints attention (flash MMA)
    joints_attn_mma<<<BHc, 256, JSMEM>>>();

    // 4) spatial attention (MMA)
    spatial_attn_mma<<<BHc * Fc, 256, SSMEM>>>();

    // 5) output GEMM
    dim3 g2(512 / 128, MROWS / 64);
    tgemm64x128<<<g2, 256>>>((const float*)pAO, w_out, b_out, out, MROWS, 512, 512);
}

// round 9
// speedup vs baseline: 1.0088x; 1.0008x over previous
#include <cuda_runtime.h>
#include <math.h>
#include <float.h>

// Problem constants
#define Bc    8
#define Fc    16
#define NSc   196
#define Jc    24
#define Hc    8
#define DHc   64
#define DIMc  512
#define ROTc  32
#define Nc    3160          // J + F*NS
#define MROWS (Bc*Nc)       // 25280
#define BHc   64            // B*H
#define NSP   3136          // F*NS
#define SKR   220           // J + NS (spatial key rows)

// -------- scratch (device globals; no runtime allocation) --------
__device__ float g_qkv[(size_t)MROWS * 1536];
__device__ float g_Q   [(size_t)BHc * Nc  * 64];
__device__ float g_Kraw[(size_t)BHc * Nc  * 64];
__device__ float g_Krope[(size_t)BHc * NSP * 64];
__device__ float g_V   [(size_t)BHc * Nc  * 64];
__device__ float g_AO  [(size_t)MROWS * 512];

// -------- tf32 helpers --------
__device__ __forceinline__ unsigned f2tf32(float x) {
    unsigned u;
    asm("cvt.rna.tf32.f32 %0, %1;" : "=r"(u) : "f"(x));
    return u;
}

__device__ __forceinline__ void mma_tf32(float* d, const unsigned* a, const unsigned* b) {
    asm volatile(
        "mma.sync.aligned.m16n8k8.row.col.f32.tf32.tf32.f32 "
        "{%0,%1,%2,%3}, {%4,%5,%6,%7}, {%8,%9}, {%0,%1,%2,%3};\n"
        : "+f"(d[0]), "+f"(d[1]), "+f"(d[2]), "+f"(d[3])
        : "r"(a[0]), "r"(a[1]), "r"(a[2]), "r"(a[3]),
          "r"(b[0]), "r"(b[1]));
}

// -------- TF32 tensor-core GEMM: C[M,N] = A[M,K] @ B[K,N] (+bias) --------
__global__ __launch_bounds__(256) void tgemm64x128(
        const float* __restrict__ A, const float* __restrict__ Bm,
        const float* __restrict__ bias, float* __restrict__ C,
        int M, int N, int K) {
    __shared__ unsigned As[64][20];
    __shared__ unsigned Bs[16][136];

    int tid  = threadIdx.x;
    int lane = tid & 31, warp = tid >> 5;
    int wm = warp >> 2, wn = warp & 3;
    int g  = lane >> 2, t = lane & 3;
    int row0 = blockIdx.y * 64;
    int col0 = blockIdx.x * 128;

    int am  = tid >> 2;
    int ak  = (tid & 3) * 4;
    int bk0 = tid >> 5;
    int bn  = (tid & 31) * 4;

    const float* Ap = A + (size_t)(row0 + am) * K + ak;
    const float* Bp0 = Bm + (size_t)bk0 * N + col0 + bn;
    const float* Bp1 = Bm + (size_t)(bk0 + 8) * N + col0 + bn;

    float acc[2][4][4];
    #pragma unroll
    for (int i = 0; i < 2; i++)
        #pragma unroll
        for (int j = 0; j < 4; j++)
            #pragma unroll
            for (int r = 0; r < 4; r++) acc[i][j][r] = 0.f;

    float4 ra  = *reinterpret_cast<const float4*>(Ap);
    float4 rb0 = *reinterpret_cast<const float4*>(Bp0);
    float4 rb1 = *reinterpret_cast<const float4*>(Bp1);

    for (int k0 = 0; k0 < K; k0 += 16) {
        *reinterpret_cast<uint4*>(&As[am][ak]) =
            make_uint4(f2tf32(ra.x), f2tf32(ra.y), f2tf32(ra.z), f2tf32(ra.w));
        *reinterpret_cast<uint4*>(&Bs[bk0][bn]) =
            make_uint4(f2tf32(rb0.x), f2tf32(rb0.y), f2tf32(rb0.z), f2tf32(rb0.w));
        *reinterpret_cast<uint4*>(&Bs[bk0 + 8][bn]) =
            make_uint4(f2tf32(rb1.x), f2tf32(rb1.y), f2tf32(rb1.z), f2tf32(rb1.w));
        __syncthreads();

        if (k0 + 16 < K) {
            Ap  += 16;
            Bp0 += (size_t)16 * N;
            Bp1 += (size_t)16 * N;
            ra  = *reinterpret_cast<const float4*>(Ap);
            rb0 = *reinterpret_cast<const float4*>(Bp0);
            rb1 = *reinterpret_cast<const float4*>(Bp1);
        }

        #pragma unroll
        for (int kk = 0; kk < 16; kk += 8) {
            unsigned af[2][4], bf[4][2];
            #pragma unroll
            for (int i = 0; i < 2; i++) {
                int r = wm * 32 + i * 16;
                af[i][0] = As[r + g][kk + t];
                af[i][1] = As[r + 8 + g][kk + t];
                af[i][2] = As[r + g][kk + 4 + t];
                af[i][3] = As[r + 8 + g][kk + 4 + t];
            }
            #pragma unroll
            for (int j = 0; j < 4; j++) {
                int c = wn * 32 + j * 8 + g;
                bf[j][0] = Bs[kk + t][c];
                bf[j][1] = Bs[kk + 4 + t][c];
            }
            #pragma unroll
            for (int i = 0; i < 2; i++)
                #pragma unroll
                for (int j = 0; j < 4; j++)
                    mma_tf32(acc[i][j], af[i], bf[j]);
        }
        __syncthreads();
    }

    #pragma unroll
    for (int i = 0; i < 2; i++) {
        #pragma unroll
        for (int j = 0; j < 4; j++) {
            int r = row0 + wm * 32 + i * 16 + g;
            int c = col0 + wn * 32 + j * 8 + 2 * t;
            float bb0 = 0.f, bb1 = 0.f;
            if (bias) { bb0 = bias[c]; bb1 = bias[c + 1]; }
            float2 o0 = make_float2(acc[i][j][0] + bb0, acc[i][j][1] + bb1);
            float2 o1 = make_float2(acc[i][j][2] + bb0, acc[i][j][3] + bb1);
            *reinterpret_cast<float2*>(C + (size_t)r * N + c) = o0;
            *reinterpret_cast<float2*>(C + (size_t)(r + 8) * N + c) = o1;
        }
    }
}

// -------- split qkv into head-major Q/Kraw/Krope/V, apply scale + RoPE --------
__global__ void split_rope_kernel(const float* __restrict__ sinp, const float* __restrict__ cosp) {
    int idx = blockIdx.x * blockDim.x + threadIdx.x;
    const int total = BHc * Nc * 64;
    if (idx >= total) return;
    int d  = idx & 63;
    int n  = (idx >> 6) % Nc;
    int bh = idx / (Nc * 64);
    int b = bh >> 3, h = bh & 7;

    size_t base = ((size_t)b * Nc + n) * 1536 + h * 64;
    float qv = g_qkv[base + d] * 0.125f;
    float kv = g_qkv[base + 512 + d];
    float vv = g_qkv[base + 1024 + d];

    size_t o = ((size_t)bh * Nc + n) * 64 + d;
    g_Kraw[o] = kv;
    g_V[o]    = vv;

    float qo = qv, ko = kv;
    if (n >= Jc) {
        int m = n - Jc;
        int s = m % NSc;
        if (d < ROTc) {
            float c  = cosp[s * ROTc + d];
            float si = sinp[s * ROTc + d];
            if ((d & 1) == 0) {
                float qp = g_qkv[base + d + 1] * 0.125f;
                float kp = g_qkv[base + 512 + d + 1];
                qo = qv * c - qp * si;
                ko = kv * c - kp * si;
            } else {
                float qp = g_qkv[base + d - 1] * 0.125f;
                float kp = g_qkv[base + 512 + d - 1];
                qo = qv * c + qp * si;
                ko = kv * c + kp * si;
            }
        }
        g_Krope[((size_t)bh * NSP + m) * 64 + d] = ko;
    }
    g_Q[o] = qo;
}

// ============ joints attention (flash, tf32 MMA): block per bh ============
// S^T[128,32] = Kchunk[128,64] @ Qt[64,32]; online softmax; O += P@V.
__global__ __launch_bounds__(256) void joints_attn_mma() {
    extern __shared__ float smem[];
    unsigned* uK = (unsigned*)smem;           // 128*68
    unsigned* uV = uK + 128 * 68;             // 128*68
    unsigned* uQ = uV + 128 * 68;             // 64*36
    float*    St = (float*)(uQ + 64 * 36);    // 128*36
    unsigned* uP = (unsigned*)(St + 128 * 36);// 32*133
    float*   red = (float*)(uP + 32 * 133);   // 256
    float*  mrow = red + 256;                 // 32
    float*   scl = mrow + 32;                 // 32
    float*  lrow = scl + 32;                  // 32

    int bh = blockIdx.x;
    int b = bh >> 3, h = bh & 7;
    int tid = threadIdx.x, lane = tid & 31, warp = tid >> 5;
    int g = lane >> 2, t = lane & 3;

    const float* Kb = g_Kraw + (size_t)bh * Nc * 64;
    const float* Vb = g_V    + (size_t)bh * Nc * 64;

    if (tid < 32) { mrow[tid] = -FLT_MAX; lrow[tid] = 0.f; }

    for (int i = tid; i < 32 * 64; i += 256) {
        int q = i >> 6, d = i & 63;
        int qq = (q < Jc) ? q : (Jc - 1);
        uQ[d * 36 + q] = f2tf32(g_Q[((size_t)bh * Nc + qq) * 64 + d]);
    }

    float oc[2][4] = {{0,0,0,0},{0,0,0,0}};

    for (int c0 = 0; c0 < Nc; c0 += 128) {
        int kn = min(128, Nc - c0);
        __syncthreads();
        for (int i = tid; i < kn * 64; i += 256) {
            int r = i >> 6, d = i & 63;
            uK[r * 68 + d] = f2tf32(Kb[(size_t)(c0 + r) * 64 + d]);
            uV[r * 68 + d] = f2tf32(Vb[(size_t)(c0 + r) * 64 + d]);
        }
        __syncthreads();

        // S^T MMA: 8 m-tiles x 4 n-tiles
        for (int tIdx = warp; tIdx < 32; tIdx += 8) {
            int mi = tIdx & 7, ni = tIdx >> 3;
            float c[4] = {0,0,0,0};
            #pragma unroll
            for (int kk = 0; kk < 8; kk++) {
                unsigned a[4], bfr[2];
                const unsigned* Ab = uK + (mi * 16) * 68 + kk * 8;
                a[0] = Ab[g * 68 + t];       a[1] = Ab[(g + 8) * 68 + t];
                a[2] = Ab[g * 68 + 4 + t];   a[3] = Ab[(g + 8) * 68 + 4 + t];
                const unsigned* Bb = uQ + (kk * 8) * 36 + ni * 8;
                bfr[0] = Bb[t * 36 + g];     bfr[1] = Bb[(4 + t) * 36 + g];
                mma_tf32(c, a, bfr);
            }
            float* Sb = St + (mi * 16) * 36 + ni * 8;
            *(float2*)(Sb + g * 36 + 2 * t)       = make_float2(c[0], c[1]);
            *(float2*)(Sb + (g + 8) * 36 + 2 * t) = make_float2(c[2], c[3]);
        }
        __syncthreads();

        // online softmax update
        {
            int q = tid & 31, s = tid >> 5;
            int j0 = s * 16, j1 = min(j0 + 16, kn);
            float lm = -FLT_MAX;
            for (int j = j0; j < j1; j++) lm = fmaxf(lm, St[j * 36 + q]);
            red[s * 32 + q] = lm;
            __syncthreads();
            float cm = red[q];
            #pragma unroll
            for (int ss = 1; ss < 8; ss++) cm = fmaxf(cm, red[ss * 32 + q]);
            float mold = mrow[q];
            float mnew = fmaxf(mold, cm);
            __syncthreads();
            float ls = 0.f;
            for (int j = j0; j < j1; j++) {
                float e = __expf(St[j * 36 + q] - mnew);
                ls += e;
                uP[q * 133 + j] = f2tf32(e);
            }
            for (int j = j1; j < j0 + 16; j++) uP[q * 133 + j] = 0u;
            red[s * 32 + q] = ls;
            __syncthreads();
            if (s == 0) {
                float tot = 0.f;
                #pragma unroll
                for (int ss = 0; ss < 8; ss++) tot += red[ss * 32 + q];
                float sc = __expf(mold - mnew);
                lrow[q] = lrow[q] * sc + tot;
                mrow[q] = mnew;
                scl[q]  = sc;
            }
        }
        __syncthreads();

        // rescale + accumulate O += P @ V  (2 tiles per warp: 2m x 8n grid)
        #pragma unroll
        for (int ti = 0; ti < 2; ti++) {
            int tIdx = warp + ti * 8;
            int mi = tIdx & 1, ni = tIdx >> 1;
            int q = mi * 16 + g;
            float s0 = scl[q], s1 = scl[q + 8];
            oc[ti][0] *= s0; oc[ti][1] *= s0; oc[ti][2] *= s1; oc[ti][3] *= s1;
            for (int kk = 0; kk < 16; kk++) {
                unsigned a[4], bfr[2];
                const unsigned* Ab = uP + (mi * 16) * 133 + kk * 8;
                a[0] = Ab[g * 133 + t];      a[1] = Ab[(g + 8) * 133 + t];
                a[2] = Ab[g * 133 + 4 + t];  a[3] = Ab[(g + 8) * 133 + 4 + t];
                const unsigned* Bb = uV + (kk * 8) * 68 + ni * 8;
                bfr[0] = Bb[t * 68 + g];     bfr[1] = Bb[(4 + t) * 68 + g];
                mma_tf32(oc[ti], a, bfr);
            }
        }
    }
    __syncthreads();

    #pragma unroll
    for (int ti = 0; ti < 2; ti++) {
        int tIdx = warp + ti * 8;
        int mi = tIdx & 1, ni = tIdx >> 1;
        int q = mi * 16 + g, d = ni * 8 + 2 * t;
        if (q < Jc) {
            float inv = 1.f / lrow[q];
            *(float2*)(g_AO + ((size_t)b * Nc + q) * 512 + h * 64 + d) =
                make_float2(oc[ti][0] * inv, oc[ti][1] * inv);
        }
        if (q + 8 < Jc) {
            float inv = 1.f / lrow[q + 8];
            *(float2*)(g_AO + ((size_t)b * Nc + q + 8) * 512 + h * 64 + d) =
                make_float2(oc[ti][2] * inv, oc[ti][3] * inv);
        }
    }
}

// ============ spatial attention (tf32 MMA): block per (bh,f) ============
// K/V resident in smem (224 rows incl 4 zero-pad); loop 7 q-tiles of 32.
__global__ __launch_bounds__(256) void spatial_attn_mma() {
    extern __shared__ float smem[];
    unsigned* uK = (unsigned*)smem;             // 224*68
    unsigned* uV = uK + 224 * 68;               // 224*68
    unsigned* uQ = uV + 224 * 68;               // 64*36
    float*    St = (float*)(uQ + 64 * 36);      // 224*36
    unsigned* uP = (unsigned*)(St + 224 * 36);  // 32*233
    float*   red = (float*)(uP + 32 * 233);     // 256
    float*  srow = red + 256;                   // 32

    int blk = blockIdx.x;
    int bh = blk >> 4, f = blk & 15;
    int b = bh >> 3, h = bh & 7;
    int tid = threadIdx.x, lane = tid & 31, warp = tid >> 5;
    int g = lane >> 2, t = lane & 3;

    const float* Krb = g_Kraw  + (size_t)bh * Nc  * 64;
    const float* Kpb = g_Krope + (size_t)bh * NSP * 64;
    const float* Vb  = g_V     + (size_t)bh * Nc  * 64;

    for (int i = tid; i < 224 * 64; i += 256) {
        int r = i >> 6, d = i & 63;
        float kv = 0.f, vv = 0.f;
        if (r < Jc) { kv = Krb[r * 64 + d]; vv = Vb[r * 64 + d]; }
        else if (r < SKR) {
            int m = f * NSc + (r - Jc);
            kv = Kpb[(size_t)m * 64 + d];
            vv = Vb[(size_t)(Jc + m) * 64 + d];
        }
        uK[r * 68 + d] = f2tf32(kv);
        uV[r * 68 + d] = f2tf32(vv);
    }
    size_t qrow0 = (size_t)bh * Nc + Jc + f * NSc;
    __syncthreads();

    for (int q0 = 0; q0 < NSc; q0 += 32) {
        for (int i = tid; i < 32 * 64; i += 256) {
            int q = i >> 6, d = i & 63;
            int qq = q0 + q; if (qq > NSc - 1) qq = NSc - 1;
            uQ[d * 36 + q] = f2tf32(g_Q[(qrow0 + qq) * 64 + d]);
        }
        __syncthreads();

        // S^T = K @ Qt : 14 m-tiles x 4 n-tiles = 56 tiles
        for (int tIdx = warp; tIdx < 56; tIdx += 8) {
            int mi = tIdx % 14, ni = tIdx / 14;
            float c[4] = {0,0,0,0};
            #pragma unroll
            for (int kk = 0; kk < 8; kk++) {
                unsigned a[4], bfr[2];
                const unsigned* Ab = uK + (mi * 16) * 68 + kk * 8;
                a[0] = Ab[g * 68 + t];       a[1] = Ab[(g + 8) * 68 + t];
                a[2] = Ab[g * 68 + 4 + t];   a[3] = Ab[(g + 8) * 68 + 4 + t];
                const unsigned* Bb = uQ + (kk * 8) * 36 + ni * 8;
                bfr[0] = Bb[t * 36 + g];     bfr[1] = Bb[(4 + t) * 36 + g];
                mma_tf32(c, a, bfr);
            }
            float* Sb = St + (mi * 16) * 36 + ni * 8;
            *(float2*)(Sb + g * 36 + 2 * t)       = make_float2(c[0], c[1]);
            *(float2*)(Sb + (g + 8) * 36 + 2 * t) = make_float2(c[2], c[3]);
        }
        __syncthreads();

        // softmax (per q over 220 keys), write unnormalized exp to uP, 1/sum in srow
        {
            int q = tid & 31, s = tid >> 5;
            int j0 = s * 28, j1 = min(j0 + 28, SKR);
            float lm = -FLT_MAX;
            for (int j = j0; j < j1; j++) lm = fmaxf(lm, St[j * 36 + q]);
            red[s * 32 + q] = lm;
            __syncthreads();
            float m = red[q];
            #pragma unroll
            for (int ss = 1; ss < 8; ss++) m = fmaxf(m, red[ss * 32 + q]);
            __syncthreads();
            float ls = 0.f;
            for (int j = j0; j < j1; j++) {
                float e = __expf(St[j * 36 + q] - m);
                ls += e;
                uP[q * 233 + j] = f2tf32(e);
            }
            if (s == 7) for (int j = SKR; j < 224; j++) uP[q * 233 + j] = 0u;
            red[s * 32 + q] = ls;
            __syncthreads();
            if (s == 0) {
                float tot = 0.f;
                #pragma unroll
                for (int ss = 0; ss < 8; ss++) tot += red[ss * 32 + q];
                srow[q] = 1.f / tot;
            }
        }
        __syncthreads();

        // O = P @ V : 2 m-tiles x 8 n-tiles
        for (int tIdx = warp; tIdx < 16; tIdx += 8) {
            int mi = tIdx & 1, ni = tIdx >> 1;
            float c[4] = {0,0,0,0};
            for (int kk = 0; kk < 28; kk++) {
                unsigned a[4], bfr[2];
                const unsigned* Ab = uP + (mi * 16) * 233 + kk * 8;
                a[0] = Ab[g * 233 + t];      a[1] = Ab[(g + 8) * 233 + t];
                a[2] = Ab[g * 233 + 4 + t];  a[3] = Ab[(g + 8) * 233 + 4 + t];
                const unsigned* Bb = uV + (kk * 8) * 68 + ni * 8;
                bfr[0] = Bb[t * 68 + g];     bfr[1] = Bb[(4 + t) * 68 + g];
                mma_tf32(c, a, bfr);
            }
            int q = mi * 16 + g, d = ni * 8 + 2 * t;
            int qq = q0 + q;
            if (qq < NSc) {
                float inv = srow[q];
                int n = Jc + f * NSc + qq;
                *(float2*)(g_AO + ((size_t)b * Nc + n) * 512 + h * 64 + d) =
                    make_float2(c[0] * inv, c[1] * inv);
            }
            if (qq + 8 < NSc) {
                float inv = srow[q + 8];
                int n = Jc + f * NSc + qq + 8;
                *(float2*)(g_AO + ((size_t)b * Nc + n) * 512 + h * 64 + d) =
                    make_float2(c[2] * inv, c[3] * inv);
            }
        }
        __syncthreads();
    }
}

// -------- launch --------
extern "C" void kernel_launch(void* const* d_in, const int* in_sizes, int n_in,
                              void* d_out, int out_size) {
    const float* x     = (const float*)d_in[0];
    const float* w_qkv = (const float*)d_in[1];
    const float* w_out = (const float*)d_in[2];
    const float* b_out = (const float*)d_in[3];
    const float* sinp  = (const float*)d_in[4];
    const float* cosp  = (const float*)d_in[5];
    float* out = (float*)d_out;

    void *pqkv = nullptr, *pAO = nullptr;
    cudaGetSymbolAddress(&pqkv, g_qkv);
    cudaGetSymbolAddress(&pAO,  g_AO);

    const int JSMEM = (128*68*2 + 64*36 + 128*36 + 32*133 + 256 + 96) * 4;
    const int SSMEM = (224*68*2 + 64*36 + 224*36 + 32*233 + 256 + 32) * 4;
    cudaFuncSetAttribute(joints_attn_mma,
                         cudaFuncAttributeMaxDynamicSharedMemorySize, JSMEM);
    cudaFuncSetAttribute(spatial_attn_mma,
                         cudaFuncAttributeMaxDynamicSharedMemorySize, SSMEM);

    // 1) QKV GEMM
    dim3 g1(1536 / 128, MROWS / 64);
    tgemm64x128<<<g1, 256>>>(x, w_qkv, nullptr, (float*)pqkv, MROWS, 1536, 512);

    // 2) split + scale + RoPE
    int total = BHc * Nc * 64;
    split_rope_kernel<<<(total + 255) / 256, 256>>>(sinp, cosp);

    // 3) joints attention (flash MMA)
    joints_attn_mma<<<BHc, 256, JSMEM>>>();

    // 4) spatial attention (MMA)
    spatial_attn_mma<<<BHc * Fc, 256, SSMEM>>>();

    // 5) output GEMM
    dim3 g2(512 / 128, MROWS / 64);
    tgemm64x128<<<g2, 256>>>((const float*)pAO, w_out, b_out, out, MROWS, 512, 512);
}

// round 10
// speedup vs baseline: 1.1150x; 1.1052x over previous
#include <cuda_runtime.h>
#include <math.h>
#include <float.h>

// Problem constants
#define Bc    8
#define Fc    16
#define NSc   196
#define Jc    24
#define Hc    8
#define DHc   64
#define DIMc  512
#define ROTc  32
#define Nc    3160          // J + F*NS
#define MROWS (Bc*Nc)       // 25280
#define BHc   64            // B*H
#define NSP   3136          // F*NS
#define SKR   220           // J + NS (spatial key rows)

// -------- scratch (device globals; no runtime allocation) --------
__device__ float g_qkv[(size_t)MROWS * 1536];
__device__ float g_Q   [(size_t)BHc * Nc  * 64];
__device__ float g_Kraw[(size_t)BHc * Nc  * 64];
__device__ float g_Krope[(size_t)BHc * NSP * 64];
__device__ float g_V   [(size_t)BHc * Nc  * 64];
__device__ float g_AO  [(size_t)MROWS * 512];

// -------- tf32 helpers --------
__device__ __forceinline__ unsigned f2tf32(float x) {
    unsigned u;
    asm("cvt.rna.tf32.f32 %0, %1;" : "=r"(u) : "f"(x));
    return u;
}

__device__ __forceinline__ void mma_tf32(float* d, const unsigned* a, const unsigned* b) {
    asm volatile(
        "mma.sync.aligned.m16n8k8.row.col.f32.tf32.tf32.f32 "
        "{%0,%1,%2,%3}, {%4,%5,%6,%7}, {%8,%9}, {%0,%1,%2,%3};\n"
        : "+f"(d[0]), "+f"(d[1]), "+f"(d[2]), "+f"(d[3])
        : "r"(a[0]), "r"(a[1]), "r"(a[2]), "r"(a[3]),
          "r"(b[0]), "r"(b[1]));
}

// -------- TF32 tensor-core GEMM: C[M,N] = A[M,K] @ B[K,N] (+bias) --------
__global__ __launch_bounds__(256) void tgemm64x128(
        const float* __restrict__ A, const float* __restrict__ Bm,
        const float* __restrict__ bias, float* __restrict__ C,
        int M, int N, int K) {
    __shared__ unsigned As[64][20];
    __shared__ unsigned Bs[16][136];

    int tid  = threadIdx.x;
    int lane = tid & 31, warp = tid >> 5;
    int wm = warp >> 2, wn = warp & 3;
    int g  = lane >> 2, t = lane & 3;
    int row0 = blockIdx.y * 64;
    int col0 = blockIdx.x * 128;

    int am  = tid >> 2;
    int ak  = (tid & 3) * 4;
    int bk0 = tid >> 5;
    int bn  = (tid & 31) * 4;

    const float* Ap = A + (size_t)(row0 + am) * K + ak;
    const float* Bp0 = Bm + (size_t)bk0 * N + col0 + bn;
    const float* Bp1 = Bm + (size_t)(bk0 + 8) * N + col0 + bn;

    float acc[2][4][4];
    #pragma unroll
    for (int i = 0; i < 2; i++)
        #pragma unroll
        for (int j = 0; j < 4; j++)
            #pragma unroll
            for (int r = 0; r < 4; r++) acc[i][j][r] = 0.f;

    float4 ra  = *reinterpret_cast<const float4*>(Ap);
    float4 rb0 = *reinterpret_cast<const float4*>(Bp0);
    float4 rb1 = *reinterpret_cast<const float4*>(Bp1);

    for (int k0 = 0; k0 < K; k0 += 16) {
        *reinterpret_cast<uint4*>(&As[am][ak]) =
            make_uint4(f2tf32(ra.x), f2tf32(ra.y), f2tf32(ra.z), f2tf32(ra.w));
        *reinterpret_cast<uint4*>(&Bs[bk0][bn]) =
            make_uint4(f2tf32(rb0.x), f2tf32(rb0.y), f2tf32(rb0.z), f2tf32(rb0.w));
        *reinterpret_cast<uint4*>(&Bs[bk0 + 8][bn]) =
            make_uint4(f2tf32(rb1.x), f2tf32(rb1.y), f2tf32(rb1.z), f2tf32(rb1.w));
        __syncthreads();

        if (k0 + 16 < K) {
            Ap  += 16;
            Bp0 += (size_t)16 * N;
            Bp1 += (size_t)16 * N;
            ra  = *reinterpret_cast<const float4*>(Ap);
            rb0 = *reinterpret_cast<const float4*>(Bp0);
            rb1 = *reinterpret_cast<const float4*>(Bp1);
        }

        #pragma unroll
        for (int kk = 0; kk < 16; kk += 8) {
            unsigned af[2][4], bf[4][2];
            #pragma unroll
            for (int i = 0; i < 2; i++) {
                int r = wm * 32 + i * 16;
                af[i][0] = As[r + g][kk + t];
                af[i][1] = As[r + 8 + g][kk + t];
                af[i][2] = As[r + g][kk + 4 + t];
                af[i][3] = As[r + 8 + g][kk + 4 + t];
            }
            #pragma unroll
            for (int j = 0; j < 4; j++) {
                int c = wn * 32 + j * 8 + g;
                bf[j][0] = Bs[kk + t][c];
                bf[j][1] = Bs[kk + 4 + t][c];
            }
            #pragma unroll
            for (int i = 0; i < 2; i++)
                #pragma unroll
                for (int j = 0; j < 4; j++)
                    mma_tf32(acc[i][j], af[i], bf[j]);
        }
        __syncthreads();
    }

    #pragma unroll
    for (int i = 0; i < 2; i++) {
        #pragma unroll
        for (int j = 0; j < 4; j++) {
            int r = row0 + wm * 32 + i * 16 + g;
            int c = col0 + wn * 32 + j * 8 + 2 * t;
            float bb0 = 0.f, bb1 = 0.f;
            if (bias) { bb0 = bias[c]; bb1 = bias[c + 1]; }
            float2 o0 = make_float2(acc[i][j][0] + bb0, acc[i][j][1] + bb1);
            float2 o1 = make_float2(acc[i][j][2] + bb0, acc[i][j][3] + bb1);
            *reinterpret_cast<float2*>(C + (size_t)r * N + c) = o0;
            *reinterpret_cast<float2*>(C + (size_t)(r + 8) * N + c) = o1;
        }
    }
}

// -------- split qkv into head-major Q/Kraw/Krope/V, apply scale + RoPE --------
__global__ void split_rope_kernel(const float* __restrict__ sinp, const float* __restrict__ cosp) {
    int idx = blockIdx.x * blockDim.x + threadIdx.x;
    const int total = BHc * Nc * 64;
    if (idx >= total) return;
    int d  = idx & 63;
    int n  = (idx >> 6) % Nc;
    int bh = idx / (Nc * 64);
    int b = bh >> 3, h = bh & 7;

    size_t base = ((size_t)b * Nc + n) * 1536 + h * 64;
    float qv = g_qkv[base + d] * 0.125f;
    float kv = g_qkv[base + 512 + d];
    float vv = g_qkv[base + 1024 + d];

    size_t o = ((size_t)bh * Nc + n) * 64 + d;
    g_Kraw[o] = kv;
    g_V[o]    = vv;

    float qo = qv, ko = kv;
    if (n >= Jc) {
        int m = n - Jc;
        int s = m % NSc;
        if (d < ROTc) {
            float c  = cosp[s * ROTc + d];
            float si = sinp[s * ROTc + d];
            if ((d & 1) == 0) {
                float qp = g_qkv[base + d + 1] * 0.125f;
                float kp = g_qkv[base + 512 + d + 1];
                qo = qv * c - qp * si;
                ko = kv * c - kp * si;
            } else {
                float qp = g_qkv[base + d - 1] * 0.125f;
                float kp = g_qkv[base + 512 + d - 1];
                qo = qv * c + qp * si;
                ko = kv * c + kp * si;
            }
        }
        g_Krope[((size_t)bh * NSP + m) * 64 + d] = ko;
    }
    g_Q[o] = qo;
}

// ============ joints attention (flash, tf32 MMA): block per bh ============
__global__ __launch_bounds__(256) void joints_attn_mma() {
    extern __shared__ float smem[];
    unsigned* uK = (unsigned*)smem;           // 128*68
    unsigned* uV = uK + 128 * 68;             // 128*68
    unsigned* uQ = uV + 128 * 68;             // 64*36
    float*    St = (float*)(uQ + 64 * 36);    // 128*36
    unsigned* uP = (unsigned*)(St + 128 * 36);// 32*133
    float*   red = (float*)(uP + 32 * 133);   // 256
    float*  mrow = red + 256;                 // 32
    float*   scl = mrow + 32;                 // 32
    float*  lrow = scl + 32;                  // 32

    int bh = blockIdx.x;
    int b = bh >> 3, h = bh & 7;
    int tid = threadIdx.x, lane = tid & 31, warp = tid >> 5;
    int g = lane >> 2, t = lane & 3;

    const float* Kb = g_Kraw + (size_t)bh * Nc * 64;
    const float* Vb = g_V    + (size_t)bh * Nc * 64;

    if (tid < 32) { mrow[tid] = -FLT_MAX; lrow[tid] = 0.f; }

    for (int i = tid; i < 32 * 64; i += 256) {
        int q = i >> 6, d = i & 63;
        int qq = (q < Jc) ? q : (Jc - 1);
        uQ[d * 36 + q] = f2tf32(g_Q[((size_t)bh * Nc + qq) * 64 + d]);
    }

    float oc[2][4] = {{0,0,0,0},{0,0,0,0}};

    for (int c0 = 0; c0 < Nc; c0 += 128) {
        int kn = min(128, Nc - c0);
        __syncthreads();
        for (int i = tid; i < kn * 64; i += 256) {
            int r = i >> 6, d = i & 63;
            uK[r * 68 + d] = f2tf32(Kb[(size_t)(c0 + r) * 64 + d]);
            uV[r * 68 + d] = f2tf32(Vb[(size_t)(c0 + r) * 64 + d]);
        }
        __syncthreads();

        for (int tIdx = warp; tIdx < 32; tIdx += 8) {
            int mi = tIdx & 7, ni = tIdx >> 3;
            float c[4] = {0,0,0,0};
            #pragma unroll
            for (int kk = 0; kk < 8; kk++) {
                unsigned a[4], bfr[2];
                const unsigned* Ab = uK + (mi * 16) * 68 + kk * 8;
                a[0] = Ab[g * 68 + t];       a[1] = Ab[(g + 8) * 68 + t];
                a[2] = Ab[g * 68 + 4 + t];   a[3] = Ab[(g + 8) * 68 + 4 + t];
                const unsigned* Bb = uQ + (kk * 8) * 36 + ni * 8;
                bfr[0] = Bb[t * 36 + g];     bfr[1] = Bb[(4 + t) * 36 + g];
                mma_tf32(c, a, bfr);
            }
            float* Sb = St + (mi * 16) * 36 + ni * 8;
            *(float2*)(Sb + g * 36 + 2 * t)       = make_float2(c[0], c[1]);
            *(float2*)(Sb + (g + 8) * 36 + 2 * t) = make_float2(c[2], c[3]);
        }
        __syncthreads();

        {
            int q = tid & 31, s = tid >> 5;
            int j0 = s * 16, j1 = min(j0 + 16, kn);
            float lm = -FLT_MAX;
            for (int j = j0; j < j1; j++) lm = fmaxf(lm, St[j * 36 + q]);
            red[s * 32 + q] = lm;
            __syncthreads();
            float cm = red[q];
            #pragma unroll
            for (int ss = 1; ss < 8; ss++) cm = fmaxf(cm, red[ss * 32 + q]);
            float mold = mrow[q];
            float mnew = fmaxf(mold, cm);
            __syncthreads();
            float ls = 0.f;
            for (int j = j0; j < j1; j++) {
                float e = __expf(St[j * 36 + q] - mnew);
                ls += e;
                uP[q * 133 + j] = f2tf32(e);
            }
            for (int j = j1; j < j0 + 16; j++) uP[q * 133 + j] = 0u;
            red[s * 32 + q] = ls;
            __syncthreads();
            if (s == 0) {
                float tot = 0.f;
                #pragma unroll
                for (int ss = 0; ss < 8; ss++) tot += red[ss * 32 + q];
                float sc = __expf(mold - mnew);
                lrow[q] = lrow[q] * sc + tot;
                mrow[q] = mnew;
                scl[q]  = sc;
            }
        }
        __syncthreads();

        #pragma unroll
        for (int ti = 0; ti < 2; ti++) {
            int tIdx = warp + ti * 8;
            int mi = tIdx & 1, ni = tIdx >> 1;
            int q = mi * 16 + g;
            float s0 = scl[q], s1 = scl[q + 8];
            oc[ti][0] *= s0; oc[ti][1] *= s0; oc[ti][2] *= s1; oc[ti][3] *= s1;
            for (int kk = 0; kk < 16; kk++) {
                unsigned a[4], bfr[2];
                const unsigned* Ab = uP + (mi * 16) * 133 + kk * 8;
                a[0] = Ab[g * 133 + t];      a[1] = Ab[(g + 8) * 133 + t];
                a[2] = Ab[g * 133 + 4 + t];  a[3] = Ab[(g + 8) * 133 + 4 + t];
                const unsigned* Bb = uV + (kk * 8) * 68 + ni * 8;
                bfr[0] = Bb[t * 68 + g];     bfr[1] = Bb[(4 + t) * 68 + g];
                mma_tf32(oc[ti], a, bfr);
            }
        }
    }
    __syncthreads();

    #pragma unroll
    for (int ti = 0; ti < 2; ti++) {
        int tIdx = warp + ti * 8;
        int mi = tIdx & 1, ni = tIdx >> 1;
        int q = mi * 16 + g, d = ni * 8 + 2 * t;
        if (q < Jc) {
            float inv = 1.f / lrow[q];
            *(float2*)(g_AO + ((size_t)b * Nc + q) * 512 + h * 64 + d) =
                make_float2(oc[ti][0] * inv, oc[ti][1] * inv);
        }
        if (q + 8 < Jc) {
            float inv = 1.f / lrow[q + 8];
            *(float2*)(g_AO + ((size_t)b * Nc + q + 8) * 512 + h * 64 + d) =
                make_float2(oc[ti][2] * inv, oc[ti][3] * inv);
        }
    }
}

// ============ spatial attention (tf32 MMA, 512 threads): block per (bh,f) ============
// 16 warps: S^T via warp-per-m-row with A-fragment reuse (3 LDS/MMA),
// softmax over 16 slices, PV exactly 1 tile per warp.
__global__ __launch_bounds__(512) void spatial_attn_mma() {
    extern __shared__ float smem[];
    unsigned* uK = (unsigned*)smem;             // 224*68
    unsigned* uV = uK + 224 * 68;               // 224*68
    unsigned* uQ = uV + 224 * 68;               // 64*36
    float*    St = (float*)(uQ + 64 * 36);      // 224*36
    unsigned* uP = (unsigned*)(St + 224 * 36);  // 32*233
    float*   red = (float*)(uP + 32 * 233);     // 512
    float*  srow = red + 512;                   // 32

    int blk = blockIdx.x;
    int bh = blk >> 4, f = blk & 15;
    int b = bh >> 3, h = bh & 7;
    int tid = threadIdx.x, lane = tid & 31, warp = tid >> 5;
    int g = lane >> 2, t = lane & 3;

    const float* Krb = g_Kraw  + (size_t)bh * Nc  * 64;
    const float* Kpb = g_Krope + (size_t)bh * NSP * 64;
    const float* Vb  = g_V     + (size_t)bh * Nc  * 64;

    for (int i = tid; i < 224 * 64; i += 512) {
        int r = i >> 6, d = i & 63;
        float kv = 0.f, vv = 0.f;
        if (r < Jc) { kv = Krb[r * 64 + d]; vv = Vb[r * 64 + d]; }
        else if (r < SKR) {
            int m = f * NSc + (r - Jc);
            kv = Kpb[(size_t)m * 64 + d];
            vv = Vb[(size_t)(Jc + m) * 64 + d];
        }
        uK[r * 68 + d] = f2tf32(kv);
        uV[r * 68 + d] = f2tf32(vv);
    }
    size_t qrow0 = (size_t)bh * Nc + Jc + f * NSc;
    __syncthreads();

    for (int q0 = 0; q0 < NSc; q0 += 32) {
        for (int i = tid; i < 32 * 64; i += 512) {
            int q = i >> 6, d = i & 63;
            int qq = q0 + q; if (qq > NSc - 1) qq = NSc - 1;
            uQ[d * 36 + q] = f2tf32(g_Q[(qrow0 + qq) * 64 + d]);
        }
        __syncthreads();

        // S^T = K @ Qt : warp mi owns a 16-row m-tile, computes all 4 n-tiles
        // with the A fragment loaded once per k-step.
        if (warp < 14) {
            int mi = warp;
            float c[4][4];
            #pragma unroll
            for (int ni = 0; ni < 4; ni++)
                #pragma unroll
                for (int r = 0; r < 4; r++) c[ni][r] = 0.f;
            #pragma unroll
            for (int kk = 0; kk < 8; kk++) {
                unsigned a[4];
                const unsigned* Ab = uK + (mi * 16) * 68 + kk * 8;
                a[0] = Ab[g * 68 + t];       a[1] = Ab[(g + 8) * 68 + t];
                a[2] = Ab[g * 68 + 4 + t];   a[3] = Ab[(g + 8) * 68 + 4 + t];
                #pragma unroll
                for (int ni = 0; ni < 4; ni++) {
                    unsigned bfr[2];
                    const unsigned* Bb = uQ + (kk * 8) * 36 + ni * 8;
                    bfr[0] = Bb[t * 36 + g];
                    bfr[1] = Bb[(4 + t) * 36 + g];
                    mma_tf32(c[ni], a, bfr);
                }
            }
            #pragma unroll
            for (int ni = 0; ni < 4; ni++) {
                float* Sb = St + (mi * 16) * 36 + ni * 8;
                *(float2*)(Sb + g * 36 + 2 * t)       = make_float2(c[ni][0], c[ni][1]);
                *(float2*)(Sb + (g + 8) * 36 + 2 * t) = make_float2(c[ni][2], c[ni][3]);
            }
        }
        __syncthreads();

        // softmax: 16 slices x 14 keys, per q over 220 keys
        {
            int q = tid & 31, s = tid >> 5;         // s in 0..15
            int j0 = s * 14, j1 = min(j0 + 14, SKR);
            float lm = -FLT_MAX;
            for (int j = j0; j < j1; j++) lm = fmaxf(lm, St[j * 36 + q]);
            red[s * 32 + q] = lm;
            __syncthreads();
            float m = red[q];
            #pragma unroll
            for (int ss = 1; ss < 16; ss++) m = fmaxf(m, red[ss * 32 + q]);
            __syncthreads();
            float ls = 0.f;
            for (int j = j0; j < j1; j++) {
                float e = __expf(St[j * 36 + q] - m);
                ls += e;
                uP[q * 233 + j] = f2tf32(e);
            }
            if (s == 15) for (int j = SKR; j < 224; j++) uP[q * 233 + j] = 0u;
            red[s * 32 + q] = ls;
            __syncthreads();
            if (s == 0) {
                float tot = 0.f;
                #pragma unroll
                for (int ss = 0; ss < 16; ss++) tot += red[ss * 32 + q];
                srow[q] = 1.f / tot;
            }
        }
        __syncthreads();

        // O = P @ V : 16 tiles (2m x 8n), exactly one per warp
        {
            int mi = warp & 1, ni = warp >> 1;
            float c[4] = {0,0,0,0};
            for (int kk = 0; kk < 28; kk++) {
                unsigned a[4], bfr[2];
                const unsigned* Ab = uP + (mi * 16) * 233 + kk * 8;
                a[0] = Ab[g * 233 + t];      a[1] = Ab[(g + 8) * 233 + t];
                a[2] = Ab[g * 233 + 4 + t];  a[3] = Ab[(g + 8) * 233 + 4 + t];
                const unsigned* Bb = uV + (kk * 8) * 68 + ni * 8;
                bfr[0] = Bb[t * 68 + g];     bfr[1] = Bb[(4 + t) * 68 + g];
                mma_tf32(c, a, bfr);
            }
            int q = mi * 16 + g, d = ni * 8 + 2 * t;
            int qq = q0 + q;
            if (qq < NSc) {
                float inv = srow[q];
                int n = Jc + f * NSc + qq;
                *(float2*)(g_AO + ((size_t)b * Nc + n) * 512 + h * 64 + d) =
                    make_float2(c[0] * inv, c[1] * inv);
            }
            if (qq + 8 < NSc) {
                float inv = srow[q + 8];
                int n = Jc + f * NSc + qq + 8;
                *(float2*)(g_AO + ((size_t)b * Nc + n) * 512 + h * 64 + d) =
                    make_float2(c[2] * inv, c[3] * inv);
            }
        }
        __syncthreads();
    }
}

// -------- launch --------
extern "C" void kernel_launch(void* const* d_in, const int* in_sizes, int n_in,
                              void* d_out, int out_size) {
    const float* x     = (const float*)d_in[0];
    const float* w_qkv = (const float*)d_in[1];
    const float* w_out = (const float*)d_in[2];
    const float* b_out = (const float*)d_in[3];
    const float* sinp  = (const float*)d_in[4];
    const float* cosp  = (const float*)d_in[5];
    float* out = (float*)d_out;

    void *pqkv = nullptr, *pAO = nullptr;
    cudaGetSymbolAddress(&pqkv, g_qkv);
    cudaGetSymbolAddress(&pAO,  g_AO);

    const int JSMEM = (128*68*2 + 64*36 + 128*36 + 32*133 + 256 + 96) * 4;
    const int SSMEM = (224*68*2 + 64*36 + 224*36 + 32*233 + 512 + 32) * 4;
    cudaFuncSetAttribute(joints_attn_mma,
                         cudaFuncAttributeMaxDynamicSharedMemorySize, JSMEM);
    cudaFuncSetAttribute(spatial_attn_mma,
                         cudaFuncAttributeMaxDynamicSharedMemorySize, SSMEM);

    // 1) QKV GEMM
    dim3 g1(1536 / 128, MROWS / 64);
    tgemm64x128<<<g1, 256>>>(x, w_qkv, nullptr, (float*)pqkv, MROWS, 1536, 512);

    // 2) split + scale + RoPE
    int total = BHc * Nc * 64;
    split_rope_kernel<<<(total + 255) / 256, 256>>>(sinp, cosp);

    // 3) joints attention (flash MMA)
    joints_attn_mma<<<BHc, 256, JSMEM>>>();

    // 4) spatial attention (MMA, 512 threads)
    spatial_attn_mma<<<BHc * Fc, 512, SSMEM>>>();

    // 5) output GEMM
    dim3 g2(512 / 128, MROWS / 64);
    tgemm64x128<<<g2, 256>>>((const float*)pAO, w_out, b_out, out, MROWS, 512, 512);
}